// round 8
// baseline (speedup 1.0000x reference)
#include <cuda_runtime.h>
#include <cstdint>
#include <math.h>

// Problem constants
#define BB 32
#define NN 1024
#define DD 1152
#define RR 4
#define MM 256   // NN/RR

#define BK 16
#define KST 20

// small tile (proven R6)
#define BM1 128
#define BN1 128
// big tile
#define BM2 256
#define BN2 128
#define SMEM_BIG (2 * (BM2 + BN2) * KST * 4)   // 61440 bytes

// ---------------- scratch ----------------
__device__ float g_xm  [(size_t)BB * MM * DD];
__device__ float g_PA  [2 * (size_t)DD * DD];    // [Wq^T ; Wo]
__device__ float g_PB  [2 * (size_t)DD * DD];    // [Wk^T ; Wv^T]
__device__ float g_GH  [2 * (size_t)DD * DD];    // [G0 = Wq^T Wk ; H = Wo Wv]
__device__ float g_T   [(size_t)BB * MM * DD];
__device__ float g_S   [(size_t)BB * NN * MM];
__device__ float g_YT  [(size_t)BB * DD * MM];
__device__ float g_c   [DD];
__device__ float g_b2  [DD];
__device__ float g_beta[(size_t)BB * MM];

// ---------------- helpers ----------------
__device__ __forceinline__ uint32_t f2tf32(float f) {
    uint32_t u;
    asm("cvt.rna.tf32.f32 %0, %1;" : "=r"(u) : "f"(f));
    return u;
}
__device__ __forceinline__ void cp_async16(uint32_t smem, const float* gmem) {
    asm volatile("cp.async.cg.shared.global [%0], [%1], 16;\n" :: "r"(smem), "l"(gmem));
}
__device__ __forceinline__ void cp_commit() {
    asm volatile("cp.async.commit_group;\n" ::: "memory");
}
__device__ __forceinline__ void mma_tf32(float c[4], const uint32_t a[4], const uint32_t b[2]) {
    asm volatile(
        "mma.sync.aligned.m16n8k8.row.col.f32.tf32.tf32.f32 "
        "{%0,%1,%2,%3}, {%4,%5,%6,%7}, {%8,%9}, {%0,%1,%2,%3};"
        : "+f"(c[0]), "+f"(c[1]), "+f"(c[2]), "+f"(c[3])
        : "r"(a[0]), "r"(a[1]), "r"(a[2]), "r"(a[3]), "r"(b[0]), "r"(b[1]));
}

// ---------------- misc kernels ----------------
__global__ __launch_bounds__(256) void merge_mean(const float* __restrict__ x,
                                                  float* __restrict__ xm) {
    const int D4 = DD / 4;
    size_t idx = (size_t)blockIdx.x * blockDim.x + threadIdx.x;
    size_t tot = (size_t)BB * MM * D4;
    if (idx >= tot) return;
    int d4 = (int)(idx % D4);
    size_t orow = idx / D4;
    int b = (int)(orow >> 8);
    int m = (int)(orow & 255);
    const float4* base = (const float4*)x + ((size_t)b * NN + (size_t)m * RR) * D4 + d4;
    float4 a0 = base[0];
    float4 a1 = base[D4];
    float4 a2 = base[2 * D4];
    float4 a3 = base[3 * D4];
    float4 o;
    o.x = 0.25f * (a0.x + a1.x + a2.x + a3.x);
    o.y = 0.25f * (a0.y + a1.y + a2.y + a3.y);
    o.z = 0.25f * (a0.z + a1.z + a2.z + a3.z);
    o.w = 0.25f * (a0.w + a1.w + a2.w + a3.w);
    ((float4*)xm)[idx] = o;
}

__global__ void transpose3(const float* __restrict__ Wq, const float* __restrict__ Wk,
                           const float* __restrict__ Wv,
                           float* __restrict__ PA0, float* __restrict__ PB0,
                           float* __restrict__ PB1) {
    __shared__ float t[32][33];
    const float* in = (blockIdx.z == 0) ? Wq : (blockIdx.z == 1) ? Wk : Wv;
    float* out = (blockIdx.z == 0) ? PA0 : (blockIdx.z == 1) ? PB0 : PB1;
    int bx = blockIdx.x * 32, by = blockIdx.y * 32;
    int x = bx + threadIdx.x;
    {
        int y = by + threadIdx.y;
#pragma unroll
        for (int dy = 0; dy < 32; dy += 8)
            t[threadIdx.y + dy][threadIdx.x] = in[(size_t)(y + dy) * DD + x];
    }
    __syncthreads();
    {
        int x2 = by + threadIdx.x;
        int y2 = bx + threadIdx.y;
#pragma unroll
        for (int dy = 0; dy < 32; dy += 8)
            out[(size_t)(y2 + dy) * DD + x2] = t[threadIdx.x][threadIdx.y + dy];
    }
}

__global__ __launch_bounds__(256) void copy4(const float4* __restrict__ in,
                                             float4* __restrict__ out, int n4) {
    int i = blockIdx.x * 256 + threadIdx.x;
    if (i < n4) out[i] = in[i];
}

__global__ __launch_bounds__(256) void rowvec(const float* __restrict__ W,
                                              const float* __restrict__ b,
                                              const float* __restrict__ b0,
                                              float* __restrict__ out) {
    int row = blockIdx.x * 8 + (threadIdx.x >> 5);
    int lane = threadIdx.x & 31;
    if (row >= DD) return;
    float s = 0.f;
    const float* wr = W + (size_t)row * DD;
    for (int d = lane; d < DD; d += 32) s += wr[d] * b[d];
#pragma unroll
    for (int o = 16; o; o >>= 1) s += __shfl_xor_sync(0xFFFFFFFFu, s, o);
    if (!lane) out[row] = b0 ? (s + b0[row]) : s;
}

__global__ __launch_bounds__(256) void betak(const float* __restrict__ xm,
                                             const float* __restrict__ c,
                                             float* __restrict__ beta, float scale) {
    int row = blockIdx.x * 8 + (threadIdx.x >> 5);
    int lane = threadIdx.x & 31;
    float s = 0.f;
    const float* p = xm + (size_t)row * DD;
    for (int d = lane; d < DD; d += 32) s += p[d] * c[d];
#pragma unroll
    for (int o = 16; o; o >>= 1) s += __shfl_xor_sync(0xFFFFFFFFu, s, o);
    if (!lane) beta[row] = s * scale;
}

// ---------------- small GEMM: 128x128 tile, 256 thr (proven R6) ----------------
__global__ __launch_bounds__(256) void gemm_s(
    const float* __restrict__ A, const float* __restrict__ Bm,
    const float* __restrict__ bias, float* __restrict__ C,
    int Ncols, int K,
    long long sA, long long sB, long long sC, long long sBias,
    float alpha)
{
    __shared__ float As[2][BM1 * KST];
    __shared__ float Bs[2][BN1 * KST];

    const int bz = blockIdx.z;
    const float* Ab = A + (size_t)bz * sA;
    const float* Bb = Bm + (size_t)bz * sB;
    float* Cb = C + (size_t)bz * sC;
    const float* bp = bias ? bias + (size_t)bz * sBias : nullptr;

    const int tid = threadIdx.x;
    const int warp = tid >> 5, lane = tid & 31;
    const int wm = warp & 1;
    const int wn = warp >> 1;
    const int rr = lane >> 2;
    const int cc = lane & 3;

    const int rowA0 = blockIdx.x * BM1;
    const int rowB0 = blockIdx.y * BN1;

    float acc[4][4][4];
#pragma unroll
    for (int i = 0; i < 4; i++)
#pragma unroll
        for (int j = 0; j < 4; j++)
#pragma unroll
            for (int k = 0; k < 4; k++) acc[i][j][k] = 0.0f;

    const int KT = K / BK;

    auto load_tile = [&](int buf, int kt) {
#pragma unroll
        for (int i = 0; i < 2; i++) {
            int c = tid + i * 256;
            int r = c >> 2;
            int kv = (c & 3) * 4;
            const float* gA = Ab + (size_t)(rowA0 + r) * K + kt * BK + kv;
            uint32_t sa = (uint32_t)__cvta_generic_to_shared(&As[buf][r * KST + kv]);
            cp_async16(sa, gA);
            const float* gB = Bb + (size_t)(rowB0 + r) * K + kt * BK + kv;
            uint32_t sb = (uint32_t)__cvta_generic_to_shared(&Bs[buf][r * KST + kv]);
            cp_async16(sb, gB);
        }
        cp_commit();
    };

    load_tile(0, 0);

    for (int kt = 0; kt < KT; kt++) {
        const int buf = kt & 1;
        if (kt + 1 < KT) {
            load_tile(buf ^ 1, kt + 1);
            asm volatile("cp.async.wait_group 1;\n" ::: "memory");
        } else {
            asm volatile("cp.async.wait_group 0;\n" ::: "memory");
        }
        __syncthreads();

        const float* As_ = &As[buf][0];
        const float* Bs_ = &Bs[buf][0];
#pragma unroll
        for (int ks = 0; ks < 2; ks++) {
            const int kb = ks * 8;
            uint32_t af[4][4], bf[4][2];
#pragma unroll
            for (int mi = 0; mi < 4; mi++) {
                int base = (wm * 64 + mi * 16 + rr) * KST + kb + cc;
                af[mi][0] = f2tf32(As_[base]);
                af[mi][1] = f2tf32(As_[base + 8 * KST]);
                af[mi][2] = f2tf32(As_[base + 4]);
                af[mi][3] = f2tf32(As_[base + 8 * KST + 4]);
            }
#pragma unroll
            for (int ni = 0; ni < 4; ni++) {
                int base = (wn * 32 + ni * 8 + rr) * KST + kb + cc;
                bf[ni][0] = f2tf32(Bs_[base]);
                bf[ni][1] = f2tf32(Bs_[base + 4]);
            }
#pragma unroll
            for (int mi = 0; mi < 4; mi++)
#pragma unroll
                for (int ni = 0; ni < 4; ni++)
                    mma_tf32(acc[mi][ni], af[mi], bf[ni]);
        }
        __syncthreads();
    }

#pragma unroll
    for (int mi = 0; mi < 4; mi++) {
#pragma unroll
        for (int ni = 0; ni < 4; ni++) {
            int gr = rowA0 + wm * 64 + mi * 16 + rr;
            int gc = rowB0 + wn * 32 + ni * 8 + 2 * cc;
            float b0v = 0.0f, b1v = 0.0f;
            if (bp) { b0v = bp[gc]; b1v = bp[gc + 1]; }
            float v00 = acc[mi][ni][0] * alpha + b0v;
            float v01 = acc[mi][ni][1] * alpha + b1v;
            float v10 = acc[mi][ni][2] * alpha + b0v;
            float v11 = acc[mi][ni][3] * alpha + b1v;
            float2* o0 = (float2*)(Cb + (size_t)gr * Ncols + gc);
            *o0 = make_float2(v00, v01);
            float2* o1 = (float2*)(Cb + (size_t)(gr + 8) * Ncols + gc);
            *o1 = make_float2(v10, v11);
        }
    }
}

// ---------------- big GEMM: 256x128 tile, 512 thr, 16 warps of 64x32 ----------------
__global__ __launch_bounds__(512) void gemm_b(
    const float* __restrict__ A, const float* __restrict__ Bm,
    const float* __restrict__ bias, float* __restrict__ C,
    int Ncols, int K,
    long long sA, long long sB, long long sC, long long sBias,
    float alpha)
{
    extern __shared__ float sm[];
    float* As[2] = {sm, sm + BM2 * KST};
    float* Bs[2] = {sm + 2 * BM2 * KST, sm + 2 * BM2 * KST + BN2 * KST};

    const int bz = blockIdx.z;
    const float* Ab = A + (size_t)bz * sA;
    const float* Bb = Bm + (size_t)bz * sB;
    float* Cb = C + (size_t)bz * sC;
    const float* bp = bias ? bias + (size_t)bz * sBias : nullptr;

    const int tid = threadIdx.x;
    const int warp = tid >> 5, lane = tid & 31;
    const int wm = warp & 3;        // 4 m-groups of 64 rows
    const int wn = warp >> 2;       // 4 n-groups of 32 cols
    const int rr = lane >> 2;
    const int cc = lane & 3;

    const int rowA0 = blockIdx.x * BM2;
    const int rowB0 = blockIdx.y * BN2;

    float acc[4][4][4];
#pragma unroll
    for (int i = 0; i < 4; i++)
#pragma unroll
        for (int j = 0; j < 4; j++)
#pragma unroll
            for (int k = 0; k < 4; k++) acc[i][j][k] = 0.0f;

    const int KT = K / BK;

    // A: 1024 chunks (2/thread), B: 512 chunks (1/thread)
    auto load_tile = [&](int buf, int kt) {
#pragma unroll
        for (int i = 0; i < 2; i++) {
            int c = tid + i * 512;
            int r = c >> 2;
            int kv = (c & 3) * 4;
            const float* gA = Ab + (size_t)(rowA0 + r) * K + kt * BK + kv;
            uint32_t sa = (uint32_t)__cvta_generic_to_shared(&As[buf][r * KST + kv]);
            cp_async16(sa, gA);
        }
        {
            int r = tid >> 2;
            int kv = (tid & 3) * 4;
            const float* gB = Bb + (size_t)(rowB0 + r) * K + kt * BK + kv;
            uint32_t sb = (uint32_t)__cvta_generic_to_shared(&Bs[buf][r * KST + kv]);
            cp_async16(sb, gB);
        }
        cp_commit();
    };

    load_tile(0, 0);

    for (int kt = 0; kt < KT; kt++) {
        const int buf = kt & 1;
        if (kt + 1 < KT) {
            load_tile(buf ^ 1, kt + 1);
            asm volatile("cp.async.wait_group 1;\n" ::: "memory");
        } else {
            asm volatile("cp.async.wait_group 0;\n" ::: "memory");
        }
        __syncthreads();

        const float* As_ = As[buf];
        const float* Bs_ = Bs[buf];
#pragma unroll
        for (int ks = 0; ks < 2; ks++) {
            const int kb = ks * 8;
            uint32_t af[4][4], bf[4][2];
#pragma unroll
            for (int mi = 0; mi < 4; mi++) {
                int base = (wm * 64 + mi * 16 + rr) * KST + kb + cc;
                af[mi][0] = f2tf32(As_[base]);
                af[mi][1] = f2tf32(As_[base + 8 * KST]);
                af[mi][2] = f2tf32(As_[base + 4]);
                af[mi][3] = f2tf32(As_[base + 8 * KST + 4]);
            }
#pragma unroll
            for (int ni = 0; ni < 4; ni++) {
                int base = (wn * 32 + ni * 8 + rr) * KST + kb + cc;
                bf[ni][0] = f2tf32(Bs_[base]);
                bf[ni][1] = f2tf32(Bs_[base + 4]);
            }
#pragma unroll
            for (int mi = 0; mi < 4; mi++)
#pragma unroll
                for (int ni = 0; ni < 4; ni++)
                    mma_tf32(acc[mi][ni], af[mi], bf[ni]);
        }
        __syncthreads();
    }

#pragma unroll
    for (int mi = 0; mi < 4; mi++) {
#pragma unroll
        for (int ni = 0; ni < 4; ni++) {
            int gr = rowA0 + wm * 64 + mi * 16 + rr;
            int gc = rowB0 + wn * 32 + ni * 8 + 2 * cc;
            float b0v = 0.0f, b1v = 0.0f;
            if (bp) { b0v = bp[gc]; b1v = bp[gc + 1]; }
            float v00 = acc[mi][ni][0] * alpha + b0v;
            float v01 = acc[mi][ni][1] * alpha + b1v;
            float v10 = acc[mi][ni][2] * alpha + b0v;
            float v11 = acc[mi][ni][3] * alpha + b1v;
            float2* o0 = (float2*)(Cb + (size_t)gr * Ncols + gc);
            *o0 = make_float2(v00, v01);
            float2* o1 = (float2*)(Cb + (size_t)(gr + 8) * Ncols + gc);
            *o1 = make_float2(v10, v11);
        }
    }
}

// ---------------- softmax ----------------
__global__ __launch_bounds__(256) void softmax256(float* __restrict__ S) {
    int row = blockIdx.x * 8 + (threadIdx.x >> 5);
    int lane = threadIdx.x & 31;
    float4* p = (float4*)(S + (size_t)row * MM);
    float4 v0 = p[lane];
    float4 v1 = p[lane + 32];

    float m = fmaxf(fmaxf(fmaxf(v0.x, v0.y), fmaxf(v0.z, v0.w)),
                    fmaxf(fmaxf(v1.x, v1.y), fmaxf(v1.z, v1.w)));
#pragma unroll
    for (int off = 16; off > 0; off >>= 1)
        m = fmaxf(m, __shfl_xor_sync(0xFFFFFFFFu, m, off));

    v0.x = __expf(v0.x - m); v0.y = __expf(v0.y - m);
    v0.z = __expf(v0.z - m); v0.w = __expf(v0.w - m);
    v1.x = __expf(v1.x - m); v1.y = __expf(v1.y - m);
    v1.z = __expf(v1.z - m); v1.w = __expf(v1.w - m);

    float s = v0.x + v0.y + v0.z + v0.w + v1.x + v1.y + v1.z + v1.w;
#pragma unroll
    for (int off = 16; off > 0; off >>= 1)
        s += __shfl_xor_sync(0xFFFFFFFFu, s, off);

    float inv = 1.0f / s;
    v0.x *= inv; v0.y *= inv; v0.z *= inv; v0.w *= inv;
    v1.x *= inv; v1.y *= inv; v1.z *= inv; v1.w *= inv;
    p[lane] = v0;
    p[lane + 32] = v1;
}

// ---------------- launch ----------------
extern "C" void kernel_launch(void* const* d_in, const int* in_sizes, int n_in,
                              void* d_out, int out_size) {
    static float *p_xm = nullptr, *p_PA, *p_PB, *p_GH, *p_T, *p_S, *p_YT,
                 *p_c, *p_b2, *p_beta;
    if (!p_xm) {
        cudaGetSymbolAddress((void**)&p_xm,   g_xm);
        cudaGetSymbolAddress((void**)&p_PA,   g_PA);
        cudaGetSymbolAddress((void**)&p_PB,   g_PB);
        cudaGetSymbolAddress((void**)&p_GH,   g_GH);
        cudaGetSymbolAddress((void**)&p_T,    g_T);
        cudaGetSymbolAddress((void**)&p_S,    g_S);
        cudaGetSymbolAddress((void**)&p_YT,   g_YT);
        cudaGetSymbolAddress((void**)&p_c,    g_c);
        cudaGetSymbolAddress((void**)&p_b2,   g_b2);
        cudaGetSymbolAddress((void**)&p_beta, g_beta);
        cudaFuncSetAttribute(gemm_b, cudaFuncAttributeMaxDynamicSharedMemorySize, SMEM_BIG);
    }

    const float* x  = (const float*)d_in[0];
    const float* Wq = (const float*)d_in[1];
    const float* bq = (const float*)d_in[2];
    const float* Wk = (const float*)d_in[3];
    const float* bk = (const float*)d_in[4];   // drops under softmax (row-constant)
    const float* Wv = (const float*)d_in[5];
    const float* bv = (const float*)d_in[6];
    const float* Wo = (const float*)d_in[7];
    const float* bo = (const float*)d_in[8];
    float* out = (float*)d_out;
    (void)bk;

    const float scale = 1.0f / sqrtf((float)DD);
    const size_t W2 = (size_t)DD * DD;
    dim3 blk(256), blk512(512);
    dim3 tblk(32, 8);

    // ---- weight prep ----
    transpose3<<<dim3(36, 36, 3), tblk>>>(Wq, Wk, Wv, p_PA, p_PB, p_PB + W2);
    copy4<<<(int)(W2 / 4 + 255) / 256, blk>>>((const float4*)Wo,
                                              (float4*)(p_PA + W2), (int)(W2 / 4));
    rowvec<<<(DD + 7) / 8, blk>>>(p_PB, bq, nullptr, p_c);      // c = Wk^T bq
    rowvec<<<(DD + 7) / 8, blk>>>(Wo, bv, bo, p_b2);            // b2 = Wo bv + bo

    // [G0 ; H] = [Wq^T@Wk ; Wo@Wv]   (1152 rows: 128-tile kernel)
    gemm_s<<<dim3(9, 9, 2), blk>>>(p_PA, p_PB, nullptr, p_GH, DD, DD,
                                   (long long)W2, (long long)W2, (long long)W2, 0, 1.0f);

    // ---- data path ----
    merge_mean<<<(BB * MM * (DD / 4)) / 256, blk>>>(x, p_xm);
    betak<<<(BB * MM) / 8, blk>>>(p_xm, p_c, p_beta, scale);

    // T = xm_flat @ G0^T   [8192, 1152]
    gemm_b<<<dim3(32, 9, 1), blk512, SMEM_BIG>>>(
        p_xm, p_GH, nullptr, p_T, DD, DD, 0, 0, 0, 0, 1.0f);

    // S[b] = scale * x[b] @ T[b]^T + beta[b,:]   [1024, 256]
    gemm_b<<<dim3(4, 2, BB), blk512, SMEM_BIG>>>(
        x, p_T, p_beta, p_S, MM, DD,
        (long long)NN * DD, (long long)MM * DD, (long long)NN * MM, MM, scale);

    // softmax
    softmax256<<<(BB * NN) / 8, blk>>>(p_S);

    // YT[b] = H @ xm[b]^T   [1152, 256]  (1152 rows: 128-tile kernel)
    gemm_s<<<dim3(9, 2, BB), blk>>>(
        p_GH + W2, p_xm, nullptr, p_YT, MM, DD,
        0, (long long)MM * DD, (long long)DD * MM, 0, 1.0f);

    // out[b] = P[b] @ YT[b]^T + b2   [1024, 1152]  (K = 256)
    gemm_b<<<dim3(4, 9, BB), blk512, SMEM_BIG>>>(
        p_S, p_YT, p_b2, out, DD, MM,
        (long long)NN * MM, (long long)DD * MM, (long long)NN * DD, 0, 1.0f);
}

// round 9
// speedup vs baseline: 1.4723x; 1.4723x over previous
#include <cuda_runtime.h>
#include <cuda.h>
#include <cstdint>
#include <math.h>

// Problem constants
#define BB 32
#define NN 1024
#define DD 1152
#define RR 4
#define MM 256   // NN/RR

#define BM 128
#define BN 128
#define BKT 32                      // K elems per TMA block (= 128B row)
#define TILE_BYTES (128 * 128)      // 16384 per operand buffer
#define SMEM_TMA (1024 + 4 * TILE_BYTES + 32)

// ---------------- scratch ----------------
__device__ float g_xm  [(size_t)BB * MM * DD];
__device__ float g_PA  [2 * (size_t)DD * DD];    // [Wq^T ; Wo]
__device__ float g_PB  [2 * (size_t)DD * DD];    // [Wk^T ; Wv^T]
__device__ float g_GH  [2 * (size_t)DD * DD];    // [G0 = Wq^T Wk ; H = Wo Wv]
__device__ float g_T   [(size_t)BB * MM * DD];
__device__ float g_S   [(size_t)BB * NN * MM];
__device__ float g_YT  [(size_t)BB * DD * MM];
__device__ float g_c   [DD];
__device__ float g_b2  [DD];
__device__ float g_beta[(size_t)BB * MM];

// ---------------- PTX helpers ----------------
__device__ __forceinline__ uint32_t smem_u32(const void* p) {
    uint32_t a;
    asm("{ .reg .u64 t; cvta.to.shared.u64 t, %1; cvt.u32.u64 %0, t; }" : "=r"(a) : "l"(p));
    return a;
}
__device__ __forceinline__ uint32_t f2tf32(float f) {
    uint32_t u;
    asm("cvt.rna.tf32.f32 %0, %1;" : "=r"(u) : "f"(f));
    return u;
}
__device__ __forceinline__ float lds32(uint32_t a) {
    float v;
    asm volatile("ld.shared.f32 %0, [%1];" : "=f"(v) : "r"(a));
    return v;
}
__device__ __forceinline__ void mma_tf32(float c[4], const uint32_t a[4], const uint32_t b[2]) {
    asm volatile(
        "mma.sync.aligned.m16n8k8.row.col.f32.tf32.tf32.f32 "
        "{%0,%1,%2,%3}, {%4,%5,%6,%7}, {%8,%9}, {%0,%1,%2,%3};"
        : "+f"(c[0]), "+f"(c[1]), "+f"(c[2]), "+f"(c[3])
        : "r"(a[0]), "r"(a[1]), "r"(a[2]), "r"(a[3]), "r"(b[0]), "r"(b[1]));
}

#define MBAR_INIT(addr, cnt) \
    asm volatile("mbarrier.init.shared.b64 [%0], %1;" :: "r"(addr), "r"(cnt) : "memory")
#define MBAR_EXPECT_TX(addr, bytes) \
    asm volatile("mbarrier.arrive.expect_tx.shared.b64 _, [%0], %1;" :: "r"(addr), "r"(bytes) : "memory")
#define MBAR_WAIT(addr, parity) do { \
    asm volatile( \
        "{\n\t.reg .pred P1;\n\t" \
        "WL_%=:\n\t" \
        "mbarrier.try_wait.parity.acquire.cta.shared::cta.b64 P1, [%0], %1, 0x989680;\n\t" \
        "@P1 bra.uni WD_%=;\n\t" \
        "bra.uni WL_%=;\n\t" \
        "WD_%=:\n\t}" \
        :: "r"(addr), "r"(parity) : "memory"); \
} while (0)
#define TMA3D(smem_addr, map_ptr, cx, cy, cz, mbar) \
    asm volatile( \
        "cp.async.bulk.tensor.3d.shared::cta.global.tile.mbarrier::complete_tx::bytes " \
        "[%0], [%1, {%2, %3, %4}], [%5];" \
        :: "r"(smem_addr), "l"(map_ptr), "r"(cx), "r"(cy), "r"(cz), "r"(mbar) : "memory")

// ---------------- misc kernels (proven R6) ----------------
__global__ __launch_bounds__(256) void merge_mean(const float* __restrict__ x,
                                                  float* __restrict__ xm) {
    const int D4 = DD / 4;
    size_t idx = (size_t)blockIdx.x * blockDim.x + threadIdx.x;
    size_t tot = (size_t)BB * MM * D4;
    if (idx >= tot) return;
    int d4 = (int)(idx % D4);
    size_t orow = idx / D4;
    int b = (int)(orow >> 8);
    int m = (int)(orow & 255);
    const float4* base = (const float4*)x + ((size_t)b * NN + (size_t)m * RR) * D4 + d4;
    float4 a0 = base[0];
    float4 a1 = base[D4];
    float4 a2 = base[2 * D4];
    float4 a3 = base[3 * D4];
    float4 o;
    o.x = 0.25f * (a0.x + a1.x + a2.x + a3.x);
    o.y = 0.25f * (a0.y + a1.y + a2.y + a3.y);
    o.z = 0.25f * (a0.z + a1.z + a2.z + a3.z);
    o.w = 0.25f * (a0.w + a1.w + a2.w + a3.w);
    ((float4*)xm)[idx] = o;
}

__global__ void transpose3(const float* __restrict__ Wq, const float* __restrict__ Wk,
                           const float* __restrict__ Wv,
                           float* __restrict__ PA0, float* __restrict__ PB0,
                           float* __restrict__ PB1) {
    __shared__ float t[32][33];
    const float* in = (blockIdx.z == 0) ? Wq : (blockIdx.z == 1) ? Wk : Wv;
    float* out = (blockIdx.z == 0) ? PA0 : (blockIdx.z == 1) ? PB0 : PB1;
    int bx = blockIdx.x * 32, by = blockIdx.y * 32;
    int x = bx + threadIdx.x;
    {
        int y = by + threadIdx.y;
#pragma unroll
        for (int dy = 0; dy < 32; dy += 8)
            t[threadIdx.y + dy][threadIdx.x] = in[(size_t)(y + dy) * DD + x];
    }
    __syncthreads();
    {
        int x2 = by + threadIdx.x;
        int y2 = bx + threadIdx.y;
#pragma unroll
        for (int dy = 0; dy < 32; dy += 8)
            out[(size_t)(y2 + dy) * DD + x2] = t[threadIdx.x][threadIdx.y + dy];
    }
}

__global__ __launch_bounds__(256) void copy4(const float4* __restrict__ in,
                                             float4* __restrict__ out, int n4) {
    int i = blockIdx.x * 256 + threadIdx.x;
    if (i < n4) out[i] = in[i];
}

__global__ __launch_bounds__(256) void rowvec(const float* __restrict__ W,
                                              const float* __restrict__ b,
                                              const float* __restrict__ b0,
                                              float* __restrict__ out) {
    int row = blockIdx.x * 8 + (threadIdx.x >> 5);
    int lane = threadIdx.x & 31;
    if (row >= DD) return;
    float s = 0.f;
    const float* wr = W + (size_t)row * DD;
    for (int d = lane; d < DD; d += 32) s += wr[d] * b[d];
#pragma unroll
    for (int o = 16; o; o >>= 1) s += __shfl_xor_sync(0xFFFFFFFFu, s, o);
    if (!lane) out[row] = b0 ? (s + b0[row]) : s;
}

__global__ __launch_bounds__(256) void betak(const float* __restrict__ xm,
                                             const float* __restrict__ c,
                                             float* __restrict__ beta, float scale) {
    int row = blockIdx.x * 8 + (threadIdx.x >> 5);
    int lane = threadIdx.x & 31;
    float s = 0.f;
    const float* p = xm + (size_t)row * DD;
    for (int d = lane; d < DD; d += 32) s += p[d] * c[d];
#pragma unroll
    for (int o = 16; o; o >>= 1) s += __shfl_xor_sync(0xFFFFFFFFu, s, o);
    if (!lane) beta[row] = s * scale;
}

__global__ __launch_bounds__(256) void softmax256(float* __restrict__ S) {
    int row = blockIdx.x * 8 + (threadIdx.x >> 5);
    int lane = threadIdx.x & 31;
    float4* p = (float4*)(S + (size_t)row * MM);
    float4 v0 = p[lane];
    float4 v1 = p[lane + 32];

    float m = fmaxf(fmaxf(fmaxf(v0.x, v0.y), fmaxf(v0.z, v0.w)),
                    fmaxf(fmaxf(v1.x, v1.y), fmaxf(v1.z, v1.w)));
#pragma unroll
    for (int off = 16; off > 0; off >>= 1)
        m = fmaxf(m, __shfl_xor_sync(0xFFFFFFFFu, m, off));

    v0.x = __expf(v0.x - m); v0.y = __expf(v0.y - m);
    v0.z = __expf(v0.z - m); v0.w = __expf(v0.w - m);
    v1.x = __expf(v1.x - m); v1.y = __expf(v1.y - m);
    v1.z = __expf(v1.z - m); v1.w = __expf(v1.w - m);

    float s = v0.x + v0.y + v0.z + v0.w + v1.x + v1.y + v1.z + v1.w;
#pragma unroll
    for (int off = 16; off > 0; off >>= 1)
        s += __shfl_xor_sync(0xFFFFFFFFu, s, off);

    float inv = 1.0f / s;
    v0.x *= inv; v0.y *= inv; v0.z *= inv; v0.w *= inv;
    v1.x *= inv; v1.y *= inv; v1.z *= inv; v1.w *= inv;
    p[lane] = v0;
    p[lane + 32] = v1;
}

// ---------------- TMA-fed tf32 GEMM: 128x128 tile, BK=32, double-buffered ----------------
// C[b][i][j] = alpha * sum_k A[b][i][k] * Bm[b][j][k]  (+ bias[b*sBias + j])
__global__ __launch_bounds__(256, 2) void gemm_t(
    const __grid_constant__ CUtensorMap tmA,
    const __grid_constant__ CUtensorMap tmB,
    const float* __restrict__ bias, float* __restrict__ C,
    int Ncols, int K, long long sC, long long sBias,
    float alpha, int zselA, int zselB)
{
    extern __shared__ __align__(16) char smraw[];
    uint32_t sb0 = smem_u32(smraw);
    const uint32_t SA = (sb0 + 1023) & ~1023u;       // 1KB-aligned for SW128
    const uint32_t abuf[2] = {SA, SA + 16384};
    const uint32_t bbuf[2] = {SA + 32768, SA + 49152};
    const uint32_t mb[2] = {SA + 65536, SA + 65544};

    const int tid = threadIdx.x, warp = tid >> 5, lane = tid & 31;
    const int wm = warp & 1, wn = warp >> 1;
    const int rr = lane >> 2, cc = lane & 3;
    const int rowA0 = blockIdx.x * BM, rowB0 = blockIdx.y * BN;
    const int bz = blockIdx.z;
    const int zA = zselA * bz, zB = zselB * bz;

    if (tid == 0) { MBAR_INIT(mb[0], 1); MBAR_INIT(mb[1], 1); }
    __syncthreads();

    const int KT = K / BKT;
    if (tid == 0) {
#pragma unroll
        for (int p = 0; p < 2; p++) {
            if (p < KT) {
                MBAR_EXPECT_TX(mb[p], 2 * TILE_BYTES);
                TMA3D(abuf[p], &tmA, p * BKT, rowA0, zA, mb[p]);
                TMA3D(bbuf[p], &tmB, p * BKT, rowB0, zB, mb[p]);
            }
        }
    }

    float acc[4][4][4];
#pragma unroll
    for (int i = 0; i < 4; i++)
#pragma unroll
        for (int j = 0; j < 4; j++)
#pragma unroll
            for (int k = 0; k < 4; k++) acc[i][j][k] = 0.0f;

    for (int kt = 0; kt < KT; kt++) {
        const int buf = kt & 1;
        MBAR_WAIT(mb[buf], (kt >> 1) & 1);

        const uint32_t Ab = abuf[buf], Bb = bbuf[buf];
#pragma unroll
        for (int ks = 0; ks < 4; ks++) {
            // SW128: element (r,k) at r*128 + ((k>>2 ^ (r&7))<<4) + (k&3)*4; r&7 == rr
            const uint32_t off0 = (uint32_t)((((2 * ks)     ^ rr) << 4) + cc * 4);
            const uint32_t off1 = (uint32_t)((((2 * ks + 1) ^ rr) << 4) + cc * 4);
            uint32_t af[4][4], bf[4][2];
#pragma unroll
            for (int mi = 0; mi < 4; mi++) {
                uint32_t ar = Ab + (uint32_t)((wm * 64 + mi * 16 + rr) * 128);
                af[mi][0] = f2tf32(lds32(ar + off0));
                af[mi][1] = f2tf32(lds32(ar + 1024 + off0));
                af[mi][2] = f2tf32(lds32(ar + off1));
                af[mi][3] = f2tf32(lds32(ar + 1024 + off1));
            }
#pragma unroll
            for (int ni = 0; ni < 4; ni++) {
                uint32_t br = Bb + (uint32_t)((wn * 32 + ni * 8 + rr) * 128);
                bf[ni][0] = f2tf32(lds32(br + off0));
                bf[ni][1] = f2tf32(lds32(br + off1));
            }
#pragma unroll
            for (int mi = 0; mi < 4; mi++)
#pragma unroll
                for (int ni = 0; ni < 4; ni++)
                    mma_tf32(acc[mi][ni], af[mi], bf[ni]);
        }
        __syncthreads();
        if (tid == 0 && kt + 2 < KT) {
            MBAR_EXPECT_TX(mb[buf], 2 * TILE_BYTES);
            TMA3D(abuf[buf], &tmA, (kt + 2) * BKT, rowA0, zA, mb[buf]);
            TMA3D(bbuf[buf], &tmB, (kt + 2) * BKT, rowB0, zB, mb[buf]);
        }
    }

    // epilogue
    float* Cb = C + (size_t)bz * sC;
    const float* bp = bias ? bias + (size_t)bz * sBias : nullptr;
#pragma unroll
    for (int mi = 0; mi < 4; mi++) {
#pragma unroll
        for (int ni = 0; ni < 4; ni++) {
            int gr = rowA0 + wm * 64 + mi * 16 + rr;
            int gc = rowB0 + wn * 32 + ni * 8 + 2 * cc;
            float b0v = 0.0f, b1v = 0.0f;
            if (bp) { b0v = bp[gc]; b1v = bp[gc + 1]; }
            float v00 = acc[mi][ni][0] * alpha + b0v;
            float v01 = acc[mi][ni][1] * alpha + b1v;
            float v10 = acc[mi][ni][2] * alpha + b0v;
            float v11 = acc[mi][ni][3] * alpha + b1v;
            float2* o0 = (float2*)(Cb + (size_t)gr * Ncols + gc);
            *o0 = make_float2(v00, v01);
            float2* o1 = (float2*)(Cb + (size_t)(gr + 8) * Ncols + gc);
            *o1 = make_float2(v10, v11);
        }
    }
}

// ---------------- host: tensor maps via driver entry point ----------------
typedef CUresult (*PFN_EncodeTiled)(
    CUtensorMap*, CUtensorMapDataType, cuuint32_t, void*,
    const cuuint64_t*, const cuuint64_t*, const cuuint32_t*, const cuuint32_t*,
    CUtensorMapInterleave, CUtensorMapSwizzle, CUtensorMapL2promotion, CUtensorMapFloatOOBfill);
static PFN_EncodeTiled g_encode = nullptr;

static void mk_map(CUtensorMap* m, const void* ptr, int K, long long rows, int batch,
                   long long batch_stride_elems) {
    cuuint64_t dims[3]    = {(cuuint64_t)K, (cuuint64_t)rows, (cuuint64_t)batch};
    cuuint64_t strides[2] = {(cuuint64_t)K * 4, (cuuint64_t)batch_stride_elems * 4};
    cuuint32_t box[3]     = {(cuuint32_t)BKT, 128u, 1u};
    cuuint32_t es[3]      = {1u, 1u, 1u};
    g_encode(m, CU_TENSOR_MAP_DATA_TYPE_FLOAT32, 3, (void*)ptr,
             dims, strides, box, es,
             CU_TENSOR_MAP_INTERLEAVE_NONE, CU_TENSOR_MAP_SWIZZLE_128B,
             CU_TENSOR_MAP_L2_PROMOTION_L2_128B, CU_TENSOR_MAP_FLOAT_OOB_FILL_NONE);
}

extern "C" void kernel_launch(void* const* d_in, const int* in_sizes, int n_in,
                              void* d_out, int out_size) {
    static bool inited = false;
    static float *p_xm, *p_PA, *p_PB, *p_GH, *p_T, *p_S, *p_YT, *p_c, *p_b2, *p_beta;
    static CUtensorMap mA_PA, mB_PB, mA_xmF, mB_G0, mA_x, mB_T, mA_H, mB_xmB, mA_S, mB_YT;

    const float* x  = (const float*)d_in[0];
    const float* Wq = (const float*)d_in[1];
    const float* bq = (const float*)d_in[2];
    const float* Wk = (const float*)d_in[3];
    const float* bk = (const float*)d_in[4];   // row-constant in logits: drops under softmax
    const float* Wv = (const float*)d_in[5];
    const float* bv = (const float*)d_in[6];
    const float* Wo = (const float*)d_in[7];
    const float* bo = (const float*)d_in[8];
    float* out = (float*)d_out;
    (void)bk;

    const size_t W2 = (size_t)DD * DD;

    if (!inited) {
        cudaGetSymbolAddress((void**)&p_xm,   g_xm);
        cudaGetSymbolAddress((void**)&p_PA,   g_PA);
        cudaGetSymbolAddress((void**)&p_PB,   g_PB);
        cudaGetSymbolAddress((void**)&p_GH,   g_GH);
        cudaGetSymbolAddress((void**)&p_T,    g_T);
        cudaGetSymbolAddress((void**)&p_S,    g_S);
        cudaGetSymbolAddress((void**)&p_YT,   g_YT);
        cudaGetSymbolAddress((void**)&p_c,    g_c);
        cudaGetSymbolAddress((void**)&p_b2,   g_b2);
        cudaGetSymbolAddress((void**)&p_beta, g_beta);

        void* fn = nullptr;
        cudaDriverEntryPointQueryResult qr;
        cudaGetDriverEntryPointByVersion("cuTensorMapEncodeTiled", &fn, 12000,
                                         cudaEnableDefault, &qr);
        g_encode = (PFN_EncodeTiled)fn;

        mk_map(&mA_PA,  p_PA,      DD, DD,       2,  (long long)W2);
        mk_map(&mB_PB,  p_PB,      DD, DD,       2,  (long long)W2);
        mk_map(&mA_xmF, p_xm,      DD, BB * MM,  1,  (long long)BB * MM * DD);
        mk_map(&mB_G0,  p_GH,      DD, DD,       1,  (long long)W2);
        mk_map(&mA_x,   x,         DD, NN,       BB, (long long)NN * DD);
        mk_map(&mB_T,   p_T,       DD, MM,       BB, (long long)MM * DD);
        mk_map(&mA_H,   p_GH + W2, DD, DD,       1,  (long long)W2);
        mk_map(&mB_xmB, p_xm,      DD, MM,       BB, (long long)MM * DD);
        mk_map(&mA_S,   p_S,       MM, NN,       BB, (long long)NN * MM);
        mk_map(&mB_YT,  p_YT,      MM, DD,       BB, (long long)DD * MM);

        cudaFuncSetAttribute(gemm_t, cudaFuncAttributeMaxDynamicSharedMemorySize, SMEM_TMA);
        inited = true;
    }

    const float scale = 1.0f / sqrtf((float)DD);
    dim3 blk(256);
    dim3 tblk(32, 8);

    // ---- weight prep ----
    transpose3<<<dim3(36, 36, 3), tblk>>>(Wq, Wk, Wv, p_PA, p_PB, p_PB + W2);
    copy4<<<(int)(W2 / 4 + 255) / 256, blk>>>((const float4*)Wo,
                                              (float4*)(p_PA + W2), (int)(W2 / 4));
    rowvec<<<(DD + 7) / 8, blk>>>(p_PB, bq, nullptr, p_c);      // c = Wk^T bq
    rowvec<<<(DD + 7) / 8, blk>>>(Wo, bv, bo, p_b2);            // b2 = Wo bv + bo

    // [G0 ; H] = [Wq^T@Wk ; Wo@Wv]
    gemm_t<<<dim3(9, 9, 2), blk, SMEM_TMA>>>(
        mA_PA, mB_PB, nullptr, p_GH, DD, DD, (long long)W2, 0, 1.0f, 1, 1);

    // ---- data path ----
    merge_mean<<<(BB * MM * (DD / 4)) / 256, blk>>>(x, p_xm);
    betak<<<(BB * MM) / 8, blk>>>(p_xm, p_c, p_beta, scale);

    // T = xm_flat @ G0^T   [8192, 1152]
    gemm_t<<<dim3(64, 9, 1), blk, SMEM_TMA>>>(
        mA_xmF, mB_G0, nullptr, p_T, DD, DD, 0, 0, 1.0f, 0, 0);

    // S[b] = scale * x[b] @ T[b]^T + beta[b,:]   [1024, 256]
    gemm_t<<<dim3(8, 2, BB), blk, SMEM_TMA>>>(
        mA_x, mB_T, p_beta, p_S, MM, DD, (long long)NN * MM, MM, scale, 1, 1);

    // softmax rows of S -> P
    softmax256<<<(BB * NN) / 8, blk>>>(p_S);

    // YT[b] = H @ xm[b]^T   [1152, 256]
    gemm_t<<<dim3(9, 2, BB), blk, SMEM_TMA>>>(
        mA_H, mB_xmB, nullptr, p_YT, MM, DD, (long long)DD * MM, 0, 1.0f, 0, 1);

    // out[b] = P[b] @ YT[b]^T + b2   [1024, 1152]  (K = 256)
    gemm_t<<<dim3(8, 9, BB), blk, SMEM_TMA>>>(
        mA_S, mB_YT, p_b2, out, DD, MM, (long long)NN * DD, 0, 1.0f, 1, 1);
}

// round 11
// speedup vs baseline: 1.4735x; 1.0008x over previous
#include <cuda_runtime.h>
#include <cuda.h>
#include <cstdint>
#include <math.h>

// Problem constants
#define BB 32
#define NN 1024
#define DD 1152
#define RR 4
#define MM 256   // NN/RR

#define BM 128
#define BN 128
#define BKT 32                      // K elems per TMA block (= 128B row)
#define TILE_BYTES (128 * 128)      // 16384 per operand buffer
#define NSTAGE 3
#define SMEM_TMA (1024 + 6 * TILE_BYTES + 64)

// ---------------- scratch ----------------
__device__ float g_xm  [(size_t)BB * MM * DD];
__device__ float g_PA  [2 * (size_t)DD * DD];    // [Wq^T ; Wo]
__device__ float g_PB  [2 * (size_t)DD * DD];    // [Wk^T ; Wv^T]
__device__ float g_GH  [2 * (size_t)DD * DD];    // [G0 = Wq^T Wk ; H = Wo Wv]
__device__ float g_T   [(size_t)BB * MM * DD];
__device__ float g_S   [(size_t)BB * NN * MM];
__device__ float g_YT  [(size_t)BB * DD * MM];
__device__ float g_c   [DD];
__device__ float g_b2  [DD];
__device__ float g_beta[(size_t)BB * MM];

// ---------------- PTX helpers ----------------
__device__ __forceinline__ uint32_t smem_u32(const void* p) {
    uint32_t a;
    asm("{ .reg .u64 t; cvta.to.shared.u64 t, %1; cvt.u32.u64 %0, t; }" : "=r"(a) : "l"(p));
    return a;
}
__device__ __forceinline__ uint32_t f2tf32(float f) {
    uint32_t u;
    asm("cvt.rna.tf32.f32 %0, %1;" : "=r"(u) : "f"(f));
    return u;
}
__device__ __forceinline__ float lds32(uint32_t a) {
    float v;
    asm volatile("ld.shared.f32 %0, [%1];" : "=f"(v) : "r"(a));
    return v;
}
__device__ __forceinline__ void mma_tf32(float c[4], const uint32_t a[4], const uint32_t b[2]) {
    asm volatile(
        "mma.sync.aligned.m16n8k8.row.col.f32.tf32.tf32.f32 "
        "{%0,%1,%2,%3}, {%4,%5,%6,%7}, {%8,%9}, {%0,%1,%2,%3};"
        : "+f"(c[0]), "+f"(c[1]), "+f"(c[2]), "+f"(c[3])
        : "r"(a[0]), "r"(a[1]), "r"(a[2]), "r"(a[3]), "r"(b[0]), "r"(b[1]));
}

#define MBAR_INIT(addr, cnt) \
    asm volatile("mbarrier.init.shared.b64 [%0], %1;" :: "r"(addr), "r"(cnt) : "memory")
#define MBAR_ARRIVE(addr) \
    asm volatile("mbarrier.arrive.shared.b64 _, [%0];" :: "r"(addr) : "memory")
#define MBAR_EXPECT_TX(addr, bytes) \
    asm volatile("mbarrier.arrive.expect_tx.shared.b64 _, [%0], %1;" :: "r"(addr), "r"(bytes) : "memory")
#define MBAR_WAIT(addr, parity) do { \
    asm volatile( \
        "{\n\t.reg .pred P1;\n\t" \
        "WL_%=:\n\t" \
        "mbarrier.try_wait.parity.acquire.cta.shared::cta.b64 P1, [%0], %1, 0x989680;\n\t" \
        "@P1 bra.uni WD_%=;\n\t" \
        "bra.uni WL_%=;\n\t" \
        "WD_%=:\n\t}" \
        :: "r"(addr), "r"(parity) : "memory"); \
} while (0)
#define TMA3D(smem_addr, map_ptr, cx, cy, cz, mbar) \
    asm volatile( \
        "cp.async.bulk.tensor.3d.shared::cta.global.tile.mbarrier::complete_tx::bytes " \
        "[%0], [%1, {%2, %3, %4}], [%5];" \
        :: "r"(smem_addr), "l"(map_ptr), "r"(cx), "r"(cy), "r"(cz), "r"(mbar) : "memory")

// ---------------- misc kernels ----------------
__global__ __launch_bounds__(256) void merge_mean(const float* __restrict__ x,
                                                  float* __restrict__ xm) {
    const int D4 = DD / 4;
    size_t idx = (size_t)blockIdx.x * blockDim.x + threadIdx.x;
    size_t tot = (size_t)BB * MM * D4;
    if (idx >= tot) return;
    int d4 = (int)(idx % D4);
    size_t orow = idx / D4;
    int b = (int)(orow >> 8);
    int m = (int)(orow & 255);
    const float4* base = (const float4*)x + ((size_t)b * NN + (size_t)m * RR) * D4 + d4;
    float4 a0 = base[0];
    float4 a1 = base[D4];
    float4 a2 = base[2 * D4];
    float4 a3 = base[3 * D4];
    float4 o;
    o.x = 0.25f * (a0.x + a1.x + a2.x + a3.x);
    o.y = 0.25f * (a0.y + a1.y + a2.y + a3.y);
    o.z = 0.25f * (a0.z + a1.z + a2.z + a3.z);
    o.w = 0.25f * (a0.w + a1.w + a2.w + a3.w);
    ((float4*)xm)[idx] = o;
}

__global__ void transpose3(const float* __restrict__ Wq, const float* __restrict__ Wk,
                           const float* __restrict__ Wv,
                           float* __restrict__ PA0, float* __restrict__ PB0,
                           float* __restrict__ PB1) {
    __shared__ float t[32][33];
    const float* in = (blockIdx.z == 0) ? Wq : (blockIdx.z == 1) ? Wk : Wv;
    float* out = (blockIdx.z == 0) ? PA0 : (blockIdx.z == 1) ? PB0 : PB1;
    int bx = blockIdx.x * 32, by = blockIdx.y * 32;
    int x = bx + threadIdx.x;
    {
        int y = by + threadIdx.y;
#pragma unroll
        for (int dy = 0; dy < 32; dy += 8)
            t[threadIdx.y + dy][threadIdx.x] = in[(size_t)(y + dy) * DD + x];
    }
    __syncthreads();
    {
        int x2 = by + threadIdx.x;
        int y2 = bx + threadIdx.y;
#pragma unroll
        for (int dy = 0; dy < 32; dy += 8)
            out[(size_t)(y2 + dy) * DD + x2] = t[threadIdx.x][threadIdx.y + dy];
    }
}

__global__ __launch_bounds__(256) void copy4(const float4* __restrict__ in,
                                             float4* __restrict__ out, int n4) {
    int i = blockIdx.x * 256 + threadIdx.x;
    if (i < n4) out[i] = in[i];
}

__global__ __launch_bounds__(256) void rowvec(const float* __restrict__ W,
                                              const float* __restrict__ b,
                                              const float* __restrict__ b0,
                                              float* __restrict__ out) {
    int row = blockIdx.x * 8 + (threadIdx.x >> 5);
    int lane = threadIdx.x & 31;
    if (row >= DD) return;
    float s = 0.f;
    const float4* wr = (const float4*)(W + (size_t)row * DD);
    const float4* bb = (const float4*)b;
    for (int d = lane; d < DD / 4; d += 32) {
        float4 w4 = wr[d], b4 = bb[d];
        s += w4.x * b4.x + w4.y * b4.y + w4.z * b4.z + w4.w * b4.w;
    }
#pragma unroll
    for (int o = 16; o; o >>= 1) s += __shfl_xor_sync(0xFFFFFFFFu, s, o);
    if (!lane) out[row] = b0 ? (s + b0[row]) : s;
}

__global__ __launch_bounds__(256) void betak(const float* __restrict__ xm,
                                             const float* __restrict__ c,
                                             float* __restrict__ beta, float scale) {
    int row = blockIdx.x * 8 + (threadIdx.x >> 5);
    int lane = threadIdx.x & 31;
    float s = 0.f;
    const float4* p = (const float4*)(xm + (size_t)row * DD);
    const float4* cc4 = (const float4*)c;
    for (int d = lane; d < DD / 4; d += 32) {
        float4 x4 = p[d], c4 = cc4[d];
        s += x4.x * c4.x + x4.y * c4.y + x4.z * c4.z + x4.w * c4.w;
    }
#pragma unroll
    for (int o = 16; o; o >>= 1) s += __shfl_xor_sync(0xFFFFFFFFu, s, o);
    if (!lane) beta[row] = s * scale;
}

__global__ __launch_bounds__(256) void softmax256(float* __restrict__ S) {
    int row = blockIdx.x * 8 + (threadIdx.x >> 5);
    int lane = threadIdx.x & 31;
    float4* p = (float4*)(S + (size_t)row * MM);
    float4 v0 = p[lane];
    float4 v1 = p[lane + 32];

    float m = fmaxf(fmaxf(fmaxf(v0.x, v0.y), fmaxf(v0.z, v0.w)),
                    fmaxf(fmaxf(v1.x, v1.y), fmaxf(v1.z, v1.w)));
#pragma unroll
    for (int off = 16; off > 0; off >>= 1)
        m = fmaxf(m, __shfl_xor_sync(0xFFFFFFFFu, m, off));

    v0.x = __expf(v0.x - m); v0.y = __expf(v0.y - m);
    v0.z = __expf(v0.z - m); v0.w = __expf(v0.w - m);
    v1.x = __expf(v1.x - m); v1.y = __expf(v1.y - m);
    v1.z = __expf(v1.z - m); v1.w = __expf(v1.w - m);

    float s = v0.x + v0.y + v0.z + v0.w + v1.x + v1.y + v1.z + v1.w;
#pragma unroll
    for (int off = 16; off > 0; off >>= 1)
        s += __shfl_xor_sync(0xFFFFFFFFu, s, off);

    float inv = 1.0f / s;
    v0.x *= inv; v0.y *= inv; v0.z *= inv; v0.w *= inv;
    v1.x *= inv; v1.y *= inv; v1.z *= inv; v1.w *= inv;
    p[lane] = v0;
    p[lane + 32] = v1;
}

// ---------------- TMA-fed tf32 GEMM: 128x128 tile, 3-stage, empty-mbarrier flow ----------------
__global__ __launch_bounds__(256, 2) void gemm_t(
    const __grid_constant__ CUtensorMap tmA,
    const __grid_constant__ CUtensorMap tmB,
    const float* __restrict__ bias, float* __restrict__ C,
    int Ncols, int K, long long sC, long long sBias,
    float alpha, int zselA, int zselB)
{
    extern __shared__ __align__(16) char smraw[];
    uint32_t sb0 = smem_u32(smraw);
    const uint32_t SA = (sb0 + 1023) & ~1023u;       // 1KB-aligned for SW128
    uint32_t abuf[NSTAGE], bbuf[NSTAGE], mbf[NSTAGE], mbe[NSTAGE];
#pragma unroll
    for (int i = 0; i < NSTAGE; i++) {
        abuf[i] = SA + i * TILE_BYTES;
        bbuf[i] = SA + (NSTAGE + i) * TILE_BYTES;
        mbf[i]  = SA + 2 * NSTAGE * TILE_BYTES + i * 8;
        mbe[i]  = SA + 2 * NSTAGE * TILE_BYTES + (NSTAGE + i) * 8;
    }

    const int tid = threadIdx.x, warp = tid >> 5, lane = tid & 31;
    const int wm = warp & 1, wn = warp >> 1;
    const int rr = lane >> 2, cc = lane & 3;
    const int rowA0 = blockIdx.x * BM, rowB0 = blockIdx.y * BN;
    const int bz = blockIdx.z;
    const int zA = zselA * bz, zB = zselB * bz;

    if (tid == 0) {
#pragma unroll
        for (int i = 0; i < NSTAGE; i++) { MBAR_INIT(mbf[i], 1); MBAR_INIT(mbe[i], 256); }
    }
    __syncthreads();

    const int KT = K / BKT;
    if (tid == 0) {
#pragma unroll
        for (int p = 0; p < NSTAGE; p++) {
            if (p < KT) {
                MBAR_EXPECT_TX(mbf[p], 2 * TILE_BYTES);
                TMA3D(abuf[p], &tmA, p * BKT, rowA0, zA, mbf[p]);
                TMA3D(bbuf[p], &tmB, p * BKT, rowB0, zB, mbf[p]);
            }
        }
    }

    float acc[4][4][4];
#pragma unroll
    for (int i = 0; i < 4; i++)
#pragma unroll
        for (int j = 0; j < 4; j++)
#pragma unroll
            for (int k = 0; k < 4; k++) acc[i][j][k] = 0.0f;

    int buf = 0, ph = 0;
    for (int kt = 0; kt < KT; kt++) {
        MBAR_WAIT(mbf[buf], ph);

        const uint32_t Ab = abuf[buf], Bb = bbuf[buf];
#pragma unroll
        for (int ks = 0; ks < 4; ks++) {
            // SW128: element (r,k) at r*128 + ((k>>2 ^ (r&7))<<4) + (k&3)*4
            const uint32_t off0 = (uint32_t)((((2 * ks)     ^ rr) << 4) + cc * 4);
            const uint32_t off1 = (uint32_t)((((2 * ks + 1) ^ rr) << 4) + cc * 4);
            uint32_t af[4][4], bf[4][2];
#pragma unroll
            for (int mi = 0; mi < 4; mi++) {
                uint32_t ar = Ab + (uint32_t)((wm * 64 + mi * 16 + rr) * 128);
                af[mi][0] = f2tf32(lds32(ar + off0));
                af[mi][1] = f2tf32(lds32(ar + 1024 + off0));
                af[mi][2] = f2tf32(lds32(ar + off1));
                af[mi][3] = f2tf32(lds32(ar + 1024 + off1));
            }
#pragma unroll
            for (int ni = 0; ni < 4; ni++) {
                uint32_t br = Bb + (uint32_t)((wn * 32 + ni * 8 + rr) * 128);
                bf[ni][0] = f2tf32(lds32(br + off0));
                bf[ni][1] = f2tf32(lds32(br + off1));
            }
#pragma unroll
            for (int mi = 0; mi < 4; mi++)
#pragma unroll
                for (int ni = 0; ni < 4; ni++)
                    mma_tf32(acc[mi][ni], af[mi], bf[ni]);
        }

        MBAR_ARRIVE(mbe[buf]);               // consumer done with this stage
        if (tid == 0 && kt + NSTAGE < KT) {
            MBAR_WAIT(mbe[buf], ph);         // all 256 consumers drained
            MBAR_EXPECT_TX(mbf[buf], 2 * TILE_BYTES);
            TMA3D(abuf[buf], &tmA, (kt + NSTAGE) * BKT, rowA0, zA, mbf[buf]);
            TMA3D(bbuf[buf], &tmB, (kt + NSTAGE) * BKT, rowB0, zB, mbf[buf]);
        }
        if (++buf == NSTAGE) { buf = 0; ph ^= 1; }
    }

    // epilogue
    float* Cb = C + (size_t)bz * sC;
    const float* bp = bias ? bias + (size_t)bz * sBias : nullptr;
#pragma unroll
    for (int mi = 0; mi < 4; mi++) {
#pragma unroll
        for (int ni = 0; ni < 4; ni++) {
            int gr = rowA0 + wm * 64 + mi * 16 + rr;
            int gc = rowB0 + wn * 32 + ni * 8 + 2 * cc;
            float b0v = 0.0f, b1v = 0.0f;
            if (bp) { b0v = bp[gc]; b1v = bp[gc + 1]; }
            float v00 = acc[mi][ni][0] * alpha + b0v;
            float v01 = acc[mi][ni][1] * alpha + b1v;
            float v10 = acc[mi][ni][2] * alpha + b0v;
            float v11 = acc[mi][ni][3] * alpha + b1v;
            float2* o0 = (float2*)(Cb + (size_t)gr * Ncols + gc);
            *o0 = make_float2(v00, v01);
            float2* o1 = (float2*)(Cb + (size_t)(gr + 8) * Ncols + gc);
            *o1 = make_float2(v10, v11);
        }
    }
}

// ---------------- host: tensor maps via driver entry point ----------------
typedef CUresult (*PFN_EncodeTiled)(
    CUtensorMap*, CUtensorMapDataType, cuuint32_t, void*,
    const cuuint64_t*, const cuuint64_t*, const cuuint32_t*, const cuuint32_t*,
    CUtensorMapInterleave, CUtensorMapSwizzle, CUtensorMapL2promotion, CUtensorMapFloatOOBfill);
static PFN_EncodeTiled g_encode = nullptr;

static void mk_map(CUtensorMap* m, const void* ptr, int K, long long rows, int batch,
                   long long batch_stride_elems) {
    cuuint64_t dims[3]    = {(cuuint64_t)K, (cuuint64_t)rows, (cuuint64_t)batch};
    cuuint64_t strides[2] = {(cuuint64_t)K * 4, (cuuint64_t)batch_stride_elems * 4};
    cuuint32_t box[3]     = {(cuuint32_t)BKT, 128u, 1u};
    cuuint32_t es[3]      = {1u, 1u, 1u};
    g_encode(m, CU_TENSOR_MAP_DATA_TYPE_FLOAT32, 3, (void*)ptr,
             dims, strides, box, es,
             CU_TENSOR_MAP_INTERLEAVE_NONE, CU_TENSOR_MAP_SWIZZLE_128B,
             CU_TENSOR_MAP_L2_PROMOTION_L2_128B, CU_TENSOR_MAP_FLOAT_OOB_FILL_NONE);
}

extern "C" void kernel_launch(void* const* d_in, const int* in_sizes, int n_in,
                              void* d_out, int out_size) {
    static bool inited = false;
    static float *p_xm, *p_PA, *p_PB, *p_GH, *p_T, *p_S, *p_YT, *p_c, *p_b2, *p_beta;
    static CUtensorMap mA_PA, mB_PB, mA_xmF, mB_G0, mA_x, mB_T, mA_H, mB_xmB, mA_S, mB_YT;

    const float* x  = (const float*)d_in[0];
    const float* Wq = (const float*)d_in[1];
    const float* bq = (const float*)d_in[2];
    const float* Wk = (const float*)d_in[3];
    const float* bk = (const float*)d_in[4];   // row-constant in logits: drops under softmax
    const float* Wv = (const float*)d_in[5];
    const float* bv = (const float*)d_in[6];
    const float* Wo = (const float*)d_in[7];
    const float* bo = (const float*)d_in[8];
    float* out = (float*)d_out;
    (void)bk;

    const size_t W2 = (size_t)DD * DD;

    if (!inited) {
        cudaGetSymbolAddress((void**)&p_xm,   g_xm);
        cudaGetSymbolAddress((void**)&p_PA,   g_PA);
        cudaGetSymbolAddress((void**)&p_PB,   g_PB);
        cudaGetSymbolAddress((void**)&p_GH,   g_GH);
        cudaGetSymbolAddress((void**)&p_T,    g_T);
        cudaGetSymbolAddress((void**)&p_S,    g_S);
        cudaGetSymbolAddress((void**)&p_YT,   g_YT);
        cudaGetSymbolAddress((void**)&p_c,    g_c);
        cudaGetSymbolAddress((void**)&p_b2,   g_b2);
        cudaGetSymbolAddress((void**)&p_beta, g_beta);

        void* fn = nullptr;
        cudaDriverEntryPointQueryResult qr;
        cudaGetDriverEntryPointByVersion("cuTensorMapEncodeTiled", &fn, 12000,
                                         cudaEnableDefault, &qr);
        g_encode = (PFN_EncodeTiled)fn;

        mk_map(&mA_PA,  p_PA,      DD, DD,       2,  (long long)W2);
        mk_map(&mB_PB,  p_PB,      DD, DD,       2,  (long long)W2);
        mk_map(&mA_xmF, p_xm,      DD, BB * MM,  1,  (long long)BB * MM * DD);
        mk_map(&mB_G0,  p_GH,      DD, DD,       1,  (long long)W2);
        mk_map(&mA_x,   x,         DD, NN,       BB, (long long)NN * DD);
        mk_map(&mB_T,   p_T,       DD, MM,       BB, (long long)MM * DD);
        mk_map(&mA_H,   p_GH + W2, DD, DD,       1,  (long long)W2);
        mk_map(&mB_xmB, p_xm,      DD, MM,       BB, (long long)MM * DD);
        mk_map(&mA_S,   p_S,       MM, NN,       BB, (long long)NN * MM);
        mk_map(&mB_YT,  p_YT,      MM, DD,       BB, (long long)DD * MM);

        cudaFuncSetAttribute(gemm_t, cudaFuncAttributeMaxDynamicSharedMemorySize, SMEM_TMA);
        inited = true;
    }

    const float scale = 1.0f / sqrtf((float)DD);
    dim3 blk(256);
    dim3 tblk(32, 8);

    // ---- weight prep ----
    transpose3<<<dim3(36, 36, 3), tblk>>>(Wq, Wk, Wv, p_PA, p_PB, p_PB + W2);
    copy4<<<(int)(W2 / 4 + 255) / 256, blk>>>((const float4*)Wo,
                                              (float4*)(p_PA + W2), (int)(W2 / 4));
    rowvec<<<(DD + 7) / 8, blk>>>(p_PB, bq, nullptr, p_c);      // c = Wk^T bq
    rowvec<<<(DD + 7) / 8, blk>>>(Wo, bv, bo, p_b2);            // b2 = Wo bv + bo

    // [G0 ; H] = [Wq^T@Wk ; Wo@Wv]
    gemm_t<<<dim3(9, 9, 2), blk, SMEM_TMA>>>(
        mA_PA, mB_PB, nullptr, p_GH, DD, DD, (long long)W2, 0, 1.0f, 1, 1);

    // ---- data path ----
    merge_mean<<<(BB * MM * (DD / 4)) / 256, blk>>>(x, p_xm);
    betak<<<(BB * MM) / 8, blk>>>(p_xm, p_c, p_beta, scale);

    // T = xm_flat @ G0^T   [8192, 1152]
    gemm_t<<<dim3(64, 9, 1), blk, SMEM_TMA>>>(
        mA_xmF, mB_G0, nullptr, p_T, DD, DD, 0, 0, 1.0f, 0, 0);

    // S[b] = scale * x[b] @ T[b]^T + beta[b,:]   [1024, 256]
    gemm_t<<<dim3(8, 2, BB), blk, SMEM_TMA>>>(
        mA_x, mB_T, p_beta, p_S, MM, DD, (long long)NN * MM, MM, scale, 1, 1);

    // softmax rows of S -> P
    softmax256<<<(BB * NN) / 8, blk>>>(p_S);

    // YT[b] = H @ xm[b]^T   [1152, 256]
    gemm_t<<<dim3(9, 2, BB), blk, SMEM_TMA>>>(
        mA_H, mB_xmB, nullptr, p_YT, MM, DD, (long long)DD * MM, 0, 1.0f, 0, 1);

    // out[b] = P[b] @ YT[b]^T + b2   [1024, 1152]  (K = 256)
    gemm_t<<<dim3(8, 9, BB), blk, SMEM_TMA>>>(
        mA_S, mB_YT, p_b2, out, DD, MM, (long long)NN * DD, 0, 1.0f, 1, 1);
}

// round 13
// speedup vs baseline: 1.6831x; 1.1422x over previous
#include <cuda_runtime.h>
#include <cuda.h>
#include <cstdint>
#include <math.h>

// Problem constants
#define BB 32
#define NN 1024
#define DD 1152
#define RR 4
#define MM 256   // NN/RR

#define BM 128
#define BN 128
#define BKT 32                      // K elems per TMA block (= 128B row)
#define TILE_BYTES (128 * 128)
#define NSTAGE 3
#define SMEM_TMA (1024 + 6 * TILE_BYTES + 64)

// ---------------- scratch ----------------
__device__ float g_xm  [(size_t)BB * MM * DD];
__device__ float g_PA  [2 * (size_t)DD * DD];    // [Wq^T ; Wo]          (tf32-rounded)
__device__ float g_PB  [2 * (size_t)DD * DD];    // [Wk^T ; Wv^T]        (tf32-rounded)
__device__ float g_GH  [2 * (size_t)DD * DD];    // [G0 ; H]             (tf32-rounded)
__device__ float g_T   [(size_t)BB * MM * DD];   // (tf32-rounded)
__device__ float g_S   [(size_t)BB * NN * MM];   // logits -> probs (probs rounded)
__device__ float g_YT  [(size_t)BB * DD * MM];   // (tf32-rounded)
__device__ float g_c   [DD];
__device__ float g_b2  [DD];
__device__ float g_beta[(size_t)BB * MM];

// ---------------- PTX helpers ----------------
__device__ __forceinline__ uint32_t smem_u32(const void* p) {
    uint32_t a;
    asm("{ .reg .u64 t; cvta.to.shared.u64 t, %1; cvt.u32.u64 %0, t; }" : "=r"(a) : "l"(p));
    return a;
}
__device__ __forceinline__ float rtf(float f) {
    uint32_t u;
    asm("cvt.rna.tf32.f32 %0, %1;" : "=r"(u) : "f"(f));
    return __uint_as_float(u);
}
template <bool CV>
__device__ __forceinline__ uint32_t ldfrag(uint32_t a) {
    uint32_t v;
    asm volatile("ld.shared.b32 %0, [%1];" : "=r"(v) : "r"(a));
    if (CV) asm("cvt.rna.tf32.f32 %0, %1;" : "+r"(v) : "f"(__uint_as_float(v)));
    return v;
}
__device__ __forceinline__ void mma_tf32(float c[4], const uint32_t a[4], const uint32_t b[2]) {
    asm volatile(
        "mma.sync.aligned.m16n8k8.row.col.f32.tf32.tf32.f32 "
        "{%0,%1,%2,%3}, {%4,%5,%6,%7}, {%8,%9}, {%0,%1,%2,%3};"
        : "+f"(c[0]), "+f"(c[1]), "+f"(c[2]), "+f"(c[3])
        : "r"(a[0]), "r"(a[1]), "r"(a[2]), "r"(a[3]), "r"(b[0]), "r"(b[1]));
}

#define MBAR_INIT(addr, cnt) \
    asm volatile("mbarrier.init.shared.b64 [%0], %1;" :: "r"(addr), "r"(cnt) : "memory")
#define MBAR_ARRIVE(addr) \
    asm volatile("mbarrier.arrive.shared.b64 _, [%0];" :: "r"(addr) : "memory")
#define MBAR_EXPECT_TX(addr, bytes) \
    asm volatile("mbarrier.arrive.expect_tx.shared.b64 _, [%0], %1;" :: "r"(addr), "r"(bytes) : "memory")
#define MBAR_WAIT(addr, parity) do { \
    asm volatile( \
        "{\n\t.reg .pred P1;\n\t" \
        "WL_%=:\n\t" \
        "mbarrier.try_wait.parity.acquire.cta.shared::cta.b64 P1, [%0], %1, 0x989680;\n\t" \
        "@P1 bra.uni WD_%=;\n\t" \
        "bra.uni WL_%=;\n\t" \
        "WD_%=:\n\t}" \
        :: "r"(addr), "r"(parity) : "memory"); \
} while (0)
#define TMA3D(smem_addr, map_ptr, cx, cy, cz, mbar) \
    asm volatile( \
        "cp.async.bulk.tensor.3d.shared::cta.global.tile.mbarrier::complete_tx::bytes " \
        "[%0], [%1, {%2, %3, %4}], [%5];" \
        :: "r"(smem_addr), "l"(map_ptr), "r"(cx), "r"(cy), "r"(cz), "r"(mbar) : "memory")

// ---------------- misc kernels (producers round to tf32) ----------------
__global__ __launch_bounds__(256) void merge_mean(const float* __restrict__ x,
                                                  float* __restrict__ xm) {
    const int D4 = DD / 4;
    size_t idx = (size_t)blockIdx.x * blockDim.x + threadIdx.x;
    size_t tot = (size_t)BB * MM * D4;
    if (idx >= tot) return;
    int d4 = (int)(idx % D4);
    size_t orow = idx / D4;
    int b = (int)(orow >> 8);
    int m = (int)(orow & 255);
    const float4* base = (const float4*)x + ((size_t)b * NN + (size_t)m * RR) * D4 + d4;
    float4 a0 = base[0];
    float4 a1 = base[D4];
    float4 a2 = base[2 * D4];
    float4 a3 = base[3 * D4];
    float4 o;
    o.x = rtf(0.25f * (a0.x + a1.x + a2.x + a3.x));
    o.y = rtf(0.25f * (a0.y + a1.y + a2.y + a3.y));
    o.z = rtf(0.25f * (a0.z + a1.z + a2.z + a3.z));
    o.w = rtf(0.25f * (a0.w + a1.w + a2.w + a3.w));
    ((float4*)xm)[idx] = o;
}

__global__ void transpose3(const float* __restrict__ Wq, const float* __restrict__ Wk,
                           const float* __restrict__ Wv,
                           float* __restrict__ PA0, float* __restrict__ PB0,
                           float* __restrict__ PB1) {
    __shared__ float t[32][33];
    const float* in = (blockIdx.z == 0) ? Wq : (blockIdx.z == 1) ? Wk : Wv;
    float* out = (blockIdx.z == 0) ? PA0 : (blockIdx.z == 1) ? PB0 : PB1;
    int bx = blockIdx.x * 32, by = blockIdx.y * 32;
    int x = bx + threadIdx.x;
    {
        int y = by + threadIdx.y;
#pragma unroll
        for (int dy = 0; dy < 32; dy += 8)
            t[threadIdx.y + dy][threadIdx.x] = in[(size_t)(y + dy) * DD + x];
    }
    __syncthreads();
    {
        int x2 = by + threadIdx.x;
        int y2 = bx + threadIdx.y;
#pragma unroll
        for (int dy = 0; dy < 32; dy += 8)
            out[(size_t)(y2 + dy) * DD + x2] = rtf(t[threadIdx.x][threadIdx.y + dy]);
    }
}

__global__ __launch_bounds__(256) void copy4r(const float4* __restrict__ in,
                                              float4* __restrict__ out, int n4) {
    int i = blockIdx.x * 256 + threadIdx.x;
    if (i >= n4) return;
    float4 v = in[i];
    v.x = rtf(v.x); v.y = rtf(v.y); v.z = rtf(v.z); v.w = rtf(v.w);
    out[i] = v;
}

__global__ __launch_bounds__(256) void rowvec(const float* __restrict__ W,
                                              const float* __restrict__ b,
                                              const float* __restrict__ b0,
                                              float* __restrict__ out) {
    int row = blockIdx.x * 8 + (threadIdx.x >> 5);
    int lane = threadIdx.x & 31;
    if (row >= DD) return;
    float s = 0.f;
    const float4* wr = (const float4*)(W + (size_t)row * DD);
    const float4* bb = (const float4*)b;
    for (int d = lane; d < DD / 4; d += 32) {
        float4 w4 = wr[d], b4 = bb[d];
        s += w4.x * b4.x + w4.y * b4.y + w4.z * b4.z + w4.w * b4.w;
    }
#pragma unroll
    for (int o = 16; o; o >>= 1) s += __shfl_xor_sync(0xFFFFFFFFu, s, o);
    if (!lane) out[row] = b0 ? (s + b0[row]) : s;
}

__global__ __launch_bounds__(256) void betak(const float* __restrict__ xm,
                                             const float* __restrict__ c,
                                             float* __restrict__ beta, float scale) {
    int row = blockIdx.x * 8 + (threadIdx.x >> 5);
    int lane = threadIdx.x & 31;
    float s = 0.f;
    const float4* p = (const float4*)(xm + (size_t)row * DD);
    const float4* cc4 = (const float4*)c;
    for (int d = lane; d < DD / 4; d += 32) {
        float4 x4 = p[d], c4 = cc4[d];
        s += x4.x * c4.x + x4.y * c4.y + x4.z * c4.z + x4.w * c4.w;
    }
#pragma unroll
    for (int o = 16; o; o >>= 1) s += __shfl_xor_sync(0xFFFFFFFFu, s, o);
    if (!lane) beta[row] = s * scale;
}

__global__ __launch_bounds__(256) void softmax256(float* __restrict__ S) {
    int row = blockIdx.x * 8 + (threadIdx.x >> 5);
    int lane = threadIdx.x & 31;
    float4* p = (float4*)(S + (size_t)row * MM);
    float4 v0 = p[lane];
    float4 v1 = p[lane + 32];

    float m = fmaxf(fmaxf(fmaxf(v0.x, v0.y), fmaxf(v0.z, v0.w)),
                    fmaxf(fmaxf(v1.x, v1.y), fmaxf(v1.z, v1.w)));
#pragma unroll
    for (int off = 16; off > 0; off >>= 1)
        m = fmaxf(m, __shfl_xor_sync(0xFFFFFFFFu, m, off));

    v0.x = __expf(v0.x - m); v0.y = __expf(v0.y - m);
    v0.z = __expf(v0.z - m); v0.w = __expf(v0.w - m);
    v1.x = __expf(v1.x - m); v1.y = __expf(v1.y - m);
    v1.z = __expf(v1.z - m); v1.w = __expf(v1.w - m);

    float s = v0.x + v0.y + v0.z + v0.w + v1.x + v1.y + v1.z + v1.w;
#pragma unroll
    for (int off = 16; off > 0; off >>= 1)
        s += __shfl_xor_sync(0xFFFFFFFFu, s, off);

    float inv = 1.0f / s;
    v0.x = rtf(v0.x * inv); v0.y = rtf(v0.y * inv);
    v0.z = rtf(v0.z * inv); v0.w = rtf(v0.w * inv);
    v1.x = rtf(v1.x * inv); v1.y = rtf(v1.y * inv);
    v1.z = rtf(v1.z * inv); v1.w = rtf(v1.w * inv);
    p[lane] = v0;
    p[lane + 32] = v1;
}

// ---------------- TMA-fed tf32 GEMM: 128x128 tile, 3-stage; CA/CB = cvt-in-loop ----------------
template <bool CA, bool CB>
__global__ __launch_bounds__(256, 2) void gemm_t(
    const __grid_constant__ CUtensorMap tmA,
    const __grid_constant__ CUtensorMap tmB,
    const float* __restrict__ bias, float* __restrict__ C,
    int Ncols, int K, long long sC, long long sBias,
    float alpha, int zselA, int zselB, int roundC)
{
    extern __shared__ __align__(16) char smraw[];
    uint32_t sb0 = smem_u32(smraw);
    const uint32_t SA = (sb0 + 1023) & ~1023u;
    uint32_t abuf[NSTAGE], bbuf[NSTAGE], mbf[NSTAGE], mbe[NSTAGE];
#pragma unroll
    for (int i = 0; i < NSTAGE; i++) {
        abuf[i] = SA + i * TILE_BYTES;
        bbuf[i] = SA + (NSTAGE + i) * TILE_BYTES;
        mbf[i]  = SA + 2 * NSTAGE * TILE_BYTES + i * 8;
        mbe[i]  = SA + 2 * NSTAGE * TILE_BYTES + (NSTAGE + i) * 8;
    }

    const int tid = threadIdx.x, warp = tid >> 5, lane = tid & 31;
    const int wm = warp & 1, wn = warp >> 1;
    const int rr = lane >> 2, cc = lane & 3;
    const int rowA0 = blockIdx.x * BM, rowB0 = blockIdx.y * BN;
    const int bz = blockIdx.z;
    const int zA = zselA * bz, zB = zselB * bz;

    if (tid == 0) {
#pragma unroll
        for (int i = 0; i < NSTAGE; i++) { MBAR_INIT(mbf[i], 1); MBAR_INIT(mbe[i], 256); }
    }
    __syncthreads();

    const int KT = K / BKT;
    if (tid == 0) {
#pragma unroll
        for (int p = 0; p < NSTAGE; p++) {
            if (p < KT) {
                MBAR_EXPECT_TX(mbf[p], 2 * TILE_BYTES);
                TMA3D(abuf[p], &tmA, p * BKT, rowA0, zA, mbf[p]);
                TMA3D(bbuf[p], &tmB, p * BKT, rowB0, zB, mbf[p]);
            }
        }
    }

    float acc[4][4][4];
#pragma unroll
    for (int i = 0; i < 4; i++)
#pragma unroll
        for (int j = 0; j < 4; j++)
#pragma unroll
            for (int k = 0; k < 4; k++) acc[i][j][k] = 0.0f;

    int buf = 0, ph = 0;
    for (int kt = 0; kt < KT; kt++) {
        MBAR_WAIT(mbf[buf], ph);

        const uint32_t Ab = abuf[buf], Bb = bbuf[buf];
#pragma unroll
        for (int ks = 0; ks < 4; ks++) {
            // SW128: element (r,k) at r*128 + ((k>>2 ^ (r&7))<<4) + (k&3)*4
            const uint32_t off0 = (uint32_t)((((2 * ks)     ^ rr) << 4) + cc * 4);
            const uint32_t off1 = (uint32_t)((((2 * ks + 1) ^ rr) << 4) + cc * 4);
            uint32_t af[4][4], bf[4][2];
#pragma unroll
            for (int mi = 0; mi < 4; mi++) {
                uint32_t ar = Ab + (uint32_t)((wm * 64 + mi * 16 + rr) * 128);
                af[mi][0] = ldfrag<CA>(ar + off0);
                af[mi][1] = ldfrag<CA>(ar + 1024 + off0);
                af[mi][2] = ldfrag<CA>(ar + off1);
                af[mi][3] = ldfrag<CA>(ar + 1024 + off1);
            }
#pragma unroll
            for (int ni = 0; ni < 4; ni++) {
                uint32_t br = Bb + (uint32_t)((wn * 32 + ni * 8 + rr) * 128);
                bf[ni][0] = ldfrag<CB>(br + off0);
                bf[ni][1] = ldfrag<CB>(br + off1);
            }
#pragma unroll
            for (int mi = 0; mi < 4; mi++)
#pragma unroll
                for (int ni = 0; ni < 4; ni++)
                    mma_tf32(acc[mi][ni], af[mi], bf[ni]);
        }

        MBAR_ARRIVE(mbe[buf]);
        if (tid == 0 && kt + NSTAGE < KT) {
            MBAR_WAIT(mbe[buf], ph);
            MBAR_EXPECT_TX(mbf[buf], 2 * TILE_BYTES);
            TMA3D(abuf[buf], &tmA, (kt + NSTAGE) * BKT, rowA0, zA, mbf[buf]);
            TMA3D(bbuf[buf], &tmB, (kt + NSTAGE) * BKT, rowB0, zB, mbf[buf]);
        }
        if (++buf == NSTAGE) { buf = 0; ph ^= 1; }
    }

    // epilogue
    float* Cb = C + (size_t)bz * sC;
    const float* bp = bias ? bias + (size_t)bz * sBias : nullptr;
#pragma unroll
    for (int mi = 0; mi < 4; mi++) {
#pragma unroll
        for (int ni = 0; ni < 4; ni++) {
            int gr = rowA0 + wm * 64 + mi * 16 + rr;
            int gc = rowB0 + wn * 32 + ni * 8 + 2 * cc;
            float b0v = 0.0f, b1v = 0.0f;
            if (bp) { b0v = bp[gc]; b1v = bp[gc + 1]; }
            float v00 = acc[mi][ni][0] * alpha + b0v;
            float v01 = acc[mi][ni][1] * alpha + b1v;
            float v10 = acc[mi][ni][2] * alpha + b0v;
            float v11 = acc[mi][ni][3] * alpha + b1v;
            if (roundC) { v00 = rtf(v00); v01 = rtf(v01); v10 = rtf(v10); v11 = rtf(v11); }
            float2* o0 = (float2*)(Cb + (size_t)gr * Ncols + gc);
            *o0 = make_float2(v00, v01);
            float2* o1 = (float2*)(Cb + (size_t)(gr + 8) * Ncols + gc);
            *o1 = make_float2(v10, v11);
        }
    }
}

// ---------------- host ----------------
typedef CUresult (*PFN_EncodeTiled)(
    CUtensorMap*, CUtensorMapDataType, cuuint32_t, void*,
    const cuuint64_t*, const cuuint64_t*, const cuuint32_t*, const cuuint32_t*,
    CUtensorMapInterleave, CUtensorMapSwizzle, CUtensorMapL2promotion, CUtensorMapFloatOOBfill);
static PFN_EncodeTiled g_encode = nullptr;

static void mk_map(CUtensorMap* m, const void* ptr, int K, long long rows, int batch,
                   long long batch_stride_elems) {
    cuuint64_t dims[3]    = {(cuuint64_t)K, (cuuint64_t)rows, (cuuint64_t)batch};
    cuuint64_t strides[2] = {(cuuint64_t)K * 4, (cuuint64_t)batch_stride_elems * 4};
    cuuint32_t box[3]     = {(cuuint32_t)BKT, 128u, 1u};
    cuuint32_t es[3]      = {1u, 1u, 1u};
    g_encode(m, CU_TENSOR_MAP_DATA_TYPE_FLOAT32, 3, (void*)ptr,
             dims, strides, box, es,
             CU_TENSOR_MAP_INTERLEAVE_NONE, CU_TENSOR_MAP_SWIZZLE_128B,
             CU_TENSOR_MAP_L2_PROMOTION_L2_128B, CU_TENSOR_MAP_FLOAT_OOB_FILL_NONE);
}

extern "C" void kernel_launch(void* const* d_in, const int* in_sizes, int n_in,
                              void* d_out, int out_size) {
    static bool inited = false;
    static float *p_xm, *p_PA, *p_PB, *p_GH, *p_T, *p_S, *p_YT, *p_c, *p_b2, *p_beta;
    static CUtensorMap mA_PA, mB_PB, mA_xmF, mB_G0, mA_x, mB_T, mA_H, mB_xmB, mA_S, mB_YT;

    const float* x  = (const float*)d_in[0];
    const float* Wq = (const float*)d_in[1];
    const float* bq = (const float*)d_in[2];
    const float* Wk = (const float*)d_in[3];
    const float* bk = (const float*)d_in[4];   // row-constant in logits: drops under softmax
    const float* Wv = (const float*)d_in[5];
    const float* bv = (const float*)d_in[6];
    const float* Wo = (const float*)d_in[7];
    const float* bo = (const float*)d_in[8];
    float* out = (float*)d_out;
    (void)bk;

    const size_t W2 = (size_t)DD * DD;

    if (!inited) {
        cudaGetSymbolAddress((void**)&p_xm,   g_xm);
        cudaGetSymbolAddress((void**)&p_PA,   g_PA);
        cudaGetSymbolAddress((void**)&p_PB,   g_PB);
        cudaGetSymbolAddress((void**)&p_GH,   g_GH);
        cudaGetSymbolAddress((void**)&p_T,    g_T);
        cudaGetSymbolAddress((void**)&p_S,    g_S);
        cudaGetSymbolAddress((void**)&p_YT,   g_YT);
        cudaGetSymbolAddress((void**)&p_c,    g_c);
        cudaGetSymbolAddress((void**)&p_b2,   g_b2);
        cudaGetSymbolAddress((void**)&p_beta, g_beta);

        void* fn = nullptr;
        cudaDriverEntryPointQueryResult qr;
        cudaGetDriverEntryPointByVersion("cuTensorMapEncodeTiled", &fn, 12000,
                                         cudaEnableDefault, &qr);
        g_encode = (PFN_EncodeTiled)fn;

        mk_map(&mA_PA,  p_PA,      DD, DD,       2,  (long long)W2);
        mk_map(&mB_PB,  p_PB,      DD, DD,       2,  (long long)W2);
        mk_map(&mA_xmF, p_xm,      DD, BB * MM,  1,  (long long)BB * MM * DD);
        mk_map(&mB_G0,  p_GH,      DD, DD,       1,  (long long)W2);
        mk_map(&mA_x,   x,         DD, NN,       BB, (long long)NN * DD);
        mk_map(&mB_T,   p_T,       DD, MM,       BB, (long long)MM * DD);
        mk_map(&mA_H,   p_GH + W2, DD, DD,       1,  (long long)W2);
        mk_map(&mB_xmB, p_xm,      DD, MM,       BB, (long long)MM * DD);
        mk_map(&mA_S,   p_S,       MM, NN,       BB, (long long)NN * MM);
        mk_map(&mB_YT,  p_YT,      MM, DD,       BB, (long long)DD * MM);

        cudaFuncSetAttribute(gemm_t<false, false>,
                             cudaFuncAttributeMaxDynamicSharedMemorySize, SMEM_TMA);
        cudaFuncSetAttribute(gemm_t<true, false>,
                             cudaFuncAttributeMaxDynamicSharedMemorySize, SMEM_TMA);
        inited = true;
    }

    const float scale = 1.0f / sqrtf((float)DD);
    dim3 blk(256);
    dim3 tblk(32, 8);

    // ---- weight prep (all outputs tf32-rounded) ----
    transpose3<<<dim3(36, 36, 3), tblk>>>(Wq, Wk, Wv, p_PA, p_PB, p_PB + W2);
    copy4r<<<(int)(W2 / 4 + 255) / 256, blk>>>((const float4*)Wo,
                                               (float4*)(p_PA + W2), (int)(W2 / 4));
    rowvec<<<(DD + 7) / 8, blk>>>(p_PB, bq, nullptr, p_c);      // c = Wk^T bq
    rowvec<<<(DD + 7) / 8, blk>>>(Wo, bv, bo, p_b2);            // b2 = Wo bv + bo

    // [G0 ; H] = [Wq^T@Wk ; Wo@Wv]  (operands rounded -> no inner CVT; round output)
    gemm_t<false, false><<<dim3(9, 9, 2), blk, SMEM_TMA>>>(
        mA_PA, mB_PB, nullptr, p_GH, DD, DD, (long long)W2, 0, 1.0f, 1, 1, 1);

    // ---- data path ----
    merge_mean<<<(BB * MM * (DD / 4)) / 256, blk>>>(x, p_xm);    // rounded
    betak<<<(BB * MM) / 8, blk>>>(p_xm, p_c, p_beta, scale);

    // T = xm_flat @ G0^T   [8192, 1152]  (rounded out)
    gemm_t<false, false><<<dim3(64, 9, 1), blk, SMEM_TMA>>>(
        mA_xmF, mB_G0, nullptr, p_T, DD, DD, 0, 0, 1.0f, 0, 0, 1);

    // S[b] = scale * x[b] @ T[b]^T + beta  (A = raw x -> CVT on A only)
    gemm_t<true, false><<<dim3(8, 2, BB), blk, SMEM_TMA>>>(
        mA_x, mB_T, p_beta, p_S, MM, DD, (long long)NN * MM, MM, scale, 1, 1, 0);

    // softmax rows of S -> P (rounded)
    softmax256<<<(BB * NN) / 8, blk>>>(p_S);

    // YT[b] = H @ xm[b]^T   [1152, 256]  (rounded out)
    gemm_t<false, false><<<dim3(9, 2, BB), blk, SMEM_TMA>>>(
        mA_H, mB_xmB, nullptr, p_YT, MM, DD, (long long)DD * MM, 0, 1.0f, 0, 1, 1);

    // out[b] = P[b] @ YT[b]^T + b2   [1024, 1152]
    gemm_t<false, false><<<dim3(8, 9, BB), blk, SMEM_TMA>>>(
        mA_S, mB_YT, p_b2, out, DD, MM, (long long)NN * DD, 0, 1.0f, 1, 1, 0);
}